// round 13
// baseline (speedup 1.0000x reference)
#include <cuda_runtime.h>
#include <cuda_fp16.h>
#include <math_constants.h>
#include <cstdint>

// Problem constants
#define PB 4
#define PT 2048
#define PC 1024
#define PH 16
#define PDK 64
#define NTOK (PB * PT)      // 8192
#define M3 (3 * PC)         // 3072

// fp16 planes. Activations split hi/lo; weights/K/V single.
__device__ __half g_xh[NTOK * PC], g_xl[NTOK * PC];
__device__ __half g_yh[NTOK * PC], g_yl[NTOK * PC];
__device__ __half g_wa[M3 * PC];
__device__ __half g_wp[PC * PC];
__device__ __half g_qh[NTOK * PC], g_ql[NTOK * PC];   // q pre-scaled by 1/8
__device__ __half g_kk[NTOK * PC];
__device__ __half g_vv[NTOK * PC];

// ---------------------------------------------------------------------------
// Helpers
// ---------------------------------------------------------------------------
__device__ __forceinline__ uint32_t smem_u32(const void* p) {
    uint32_t a;
    asm("{ .reg .u64 t; cvta.to.shared.u64 t, %1; cvt.u32.u64 %0, t; }"
        : "=r"(a) : "l"(p));
    return a;
}
__device__ __forceinline__ void cp16(uint32_t dst, const void* src) {
    asm volatile("cp.async.cg.shared.global [%0], [%1], 16;"
                 :: "r"(dst), "l"(src));
}
#define CP_COMMIT() asm volatile("cp.async.commit_group;" ::: "memory")
#define CP_WAIT(n)  asm volatile("cp.async.wait_group %0;" :: "n"(n) : "memory")

__device__ __forceinline__ void ldsm_x4(uint32_t addr, uint32_t& r0, uint32_t& r1,
                                        uint32_t& r2, uint32_t& r3) {
    asm volatile("ldmatrix.sync.aligned.m8n8.x4.shared.b16 {%0,%1,%2,%3}, [%4];"
                 : "=r"(r0), "=r"(r1), "=r"(r2), "=r"(r3) : "r"(addr));
}
__device__ __forceinline__ void ldsm_x4t(uint32_t addr, uint32_t& r0, uint32_t& r1,
                                         uint32_t& r2, uint32_t& r3) {
    asm volatile("ldmatrix.sync.aligned.m8n8.x4.trans.shared.b16 {%0,%1,%2,%3}, [%4];"
                 : "=r"(r0), "=r"(r1), "=r"(r2), "=r"(r3) : "r"(addr));
}
__device__ __forceinline__ void mma16816(float* c, const uint32_t* a,
                                         uint32_t b0, uint32_t b1) {
    asm volatile(
        "mma.sync.aligned.m16n8k16.row.col.f32.f16.f16.f32 "
        "{%0,%1,%2,%3}, {%4,%5,%6,%7}, {%8,%9}, {%0,%1,%2,%3};"
        : "+f"(c[0]), "+f"(c[1]), "+f"(c[2]), "+f"(c[3])
        : "r"(a[0]), "r"(a[1]), "r"(a[2]), "r"(a[3]), "r"(b0), "r"(b1));
}
// fp32 pair -> fp16 hi + fp16 lo (lo = residual)
__device__ __forceinline__ void pack_split_h(float a, float b, uint32_t& hi, uint32_t& lo) {
    __half2 h = __floats2half2_rn(a, b);
    __half2 l = __floats2half2_rn(a - __low2float(h), b - __high2float(h));
    hi = *(const uint32_t*)&h;
    lo = *(const uint32_t*)&l;
}
__device__ __forceinline__ uint32_t pack_h2(float a, float b) {
    __half2 h = __floats2half2_rn(a, b);
    return *(const uint32_t*)&h;
}

// ---------------------------------------------------------------------------
// Conversions
// ---------------------------------------------------------------------------
__global__ __launch_bounds__(256) void conv_split_kernel(
    const float* __restrict__ src, __half* __restrict__ hi, __half* __restrict__ lo)
{
    const int i = (blockIdx.x * 256 + threadIdx.x) * 4;
    float4 v = *(const float4*)(src + i);
    uint32_t h0, l0, h1, l1;
    pack_split_h(v.x, v.y, h0, l0);
    pack_split_h(v.z, v.w, h1, l1);
    *(uint2*)(hi + i) = make_uint2(h0, h1);
    *(uint2*)(lo + i) = make_uint2(l0, l1);
}
__global__ __launch_bounds__(256) void conv_single_kernel(
    const float* __restrict__ src, __half* __restrict__ dst)
{
    const int i = (blockIdx.x * 256 + threadIdx.x) * 4;
    float4 v = *(const float4*)(src + i);
    *(uint2*)(dst + i) = make_uint2(pack_h2(v.x, v.y), pack_h2(v.z, v.w));
}

// ---------------------------------------------------------------------------
// Dense GEMM: D[m=token][n=feature] = (Ah+Al) * B^T + bias
// Block 128x128, K-chunk 64 per stage, 2 stages, 3 smem planes, 2 CTAs/SM.
// Hi-pass / lo-pass MMA scheduling (16 independent MMAs between RAW reuse).
// ---------------------------------------------------------------------------
#define GROWB 144                   // 64 halves = 128B + 16B pad
#define PLB (128 * GROWB)           // 18432 per plane
#define STAGEB (3 * PLB)            // Ah, Al, B
#define GK_SMEM (2 * STAGEB)        // 110592

__device__ __forceinline__ void gk_issue(
    const __half* const* srcs, uint32_t sbase, int st, int ks, int tid)
{
    #pragma unroll
    for (int t = 0; t < 12; t++) {
        const int flat = t * 256 + tid;
        const int p = flat >> 10;
        const int ch = flat & 1023;
        const int row = ch >> 3, q = ch & 7;
        cp16(sbase + st * STAGEB + p * PLB + row * GROWB + (q << 4),
             srcs[p] + (size_t)row * PC + ks * 64 + q * 8);
    }
}

template <int MODE>
__global__ __launch_bounds__(256, 2) void tc_gemm_kernel(
    const __half* __restrict__ Ah_g, const __half* __restrict__ Al_g,
    const __half* __restrict__ B_g,
    const float* __restrict__ bias, float* __restrict__ outp)
{
    extern __shared__ __align__(16) char smem[];
    const uint32_t sbase = smem_u32(smem);
    const int tid = threadIdx.x;
    const int wid = tid >> 5, lid = tid & 31;
    const int wm = wid >> 2, wn = wid & 3;
    const int fb = blockIdx.x * 128;
    const int mb = blockIdx.y * 128;

    const __half* srcs[3] = { Ah_g + (size_t)mb * PC, Al_g + (size_t)mb * PC,
                              B_g + (size_t)fb * PC };

    float c[4][4][4];
    #pragma unroll
    for (int i = 0; i < 4; i++)
        #pragma unroll
        for (int j = 0; j < 4; j++)
            #pragma unroll
            for (int e = 0; e < 4; e++) c[i][j][e] = 0.0f;

    gk_issue(srcs, sbase, 0, 0, tid);
    CP_COMMIT();

    const int lr = lid & 15;
    const int lh = lid >> 4;

    for (int ks = 0; ks < 16; ks++) {
        const int cur = ks & 1;
        if (ks + 1 < 16) {
            gk_issue(srcs, sbase, (ks + 1) & 1, ks + 1, tid);
            CP_COMMIT();
            CP_WAIT(1);
        } else {
            CP_WAIT(0);
        }
        __syncthreads();

        const uint32_t stb = sbase + cur * STAGEB;
        #pragma unroll
        for (int k16 = 0; k16 < 4; k16++) {
            const uint32_t colb = (uint32_t)(k16 * 32 + lh * 16);
            uint32_t ah[4][4], al[4][4];
            #pragma unroll
            for (int mt = 0; mt < 4; mt++) {
                const uint32_t ra = (wm * 64 + mt * 16 + lr) * GROWB + colb;
                ldsm_x4(stb + 0 * PLB + ra, ah[mt][0], ah[mt][1], ah[mt][2], ah[mt][3]);
                ldsm_x4(stb + 1 * PLB + ra, al[mt][0], al[mt][1], al[mt][2], al[mt][3]);
            }
            uint32_t bf[4][2];
            #pragma unroll
            for (int np = 0; np < 2; np++) {
                const uint32_t rb = (wn * 32 + np * 16 + lr) * GROWB + colb;
                uint32_t r0, r1, r2, r3;
                ldsm_x4(stb + 2 * PLB + rb, r0, r1, r2, r3);
                bf[np * 2][0] = r0; bf[np * 2][1] = r2;
                bf[np * 2 + 1][0] = r1; bf[np * 2 + 1][1] = r3;
            }
            // hi pass: 16 independent MMAs
            #pragma unroll
            for (int mt = 0; mt < 4; mt++)
                #pragma unroll
                for (int nt = 0; nt < 4; nt++)
                    mma16816(c[mt][nt], ah[mt], bf[nt][0], bf[nt][1]);
            // lo pass: 16 independent MMAs, RAW distance 16
            #pragma unroll
            for (int mt = 0; mt < 4; mt++)
                #pragma unroll
                for (int nt = 0; nt < 4; nt++)
                    mma16816(c[mt][nt], al[mt], bf[nt][0], bf[nt][1]);
        }
        __syncthreads();
    }

    const int r0 = lid >> 2;
    const int c0 = (lid & 3) << 1;
    #pragma unroll
    for (int mt = 0; mt < 4; mt++) {
        #pragma unroll
        for (int nt = 0; nt < 4; nt++) {
            const int f = fb + wn * 32 + nt * 8 + c0;
            const float2 b2 = *(const float2*)(bias + f);
            const int tok0 = mb + wm * 64 + mt * 16 + r0;
            float2 v0 = make_float2(c[mt][nt][0] + b2.x, c[mt][nt][1] + b2.y);
            float2 v1 = make_float2(c[mt][nt][2] + b2.x, c[mt][nt][3] + b2.y);
            if (MODE == 0) {
                const int sec = f >> 10;
                const int cc = f & (PC - 1);
                const int hh = cc >> 6, d = cc & 63;
                const int b = tok0 >> 11;
                const int tk = tok0 & (PT - 1);
                const size_t base = (((size_t)b * PH + hh) * PT + tk) * PDK + d;
                if (sec == 0) {
                    uint32_t h, l;
                    pack_split_h(v0.x * 0.125f, v0.y * 0.125f, h, l);
                    *(uint32_t*)(g_qh + base) = h;
                    *(uint32_t*)(g_ql + base) = l;
                    pack_split_h(v1.x * 0.125f, v1.y * 0.125f, h, l);
                    *(uint32_t*)(g_qh + base + 8 * PDK) = h;
                    *(uint32_t*)(g_ql + base + 8 * PDK) = l;
                } else {
                    __half* dst = (sec == 1) ? g_kk : g_vv;
                    *(uint32_t*)(dst + base) = pack_h2(v0.x, v0.y);
                    *(uint32_t*)(dst + base + 8 * PDK) = pack_h2(v1.x, v1.y);
                }
            } else {
                *(float2*)(outp + (size_t)tok0 * PC + f) = v0;
                *(float2*)(outp + (size_t)(tok0 + 8) * PC + f) = v1;
            }
        }
    }
}

// ---------------------------------------------------------------------------
// Flash attention. Br=128, Bc=64, dk=64. Q hi/lo fp16 (pre-scaled); K,V single.
// Hi-pass / lo-pass MMA scheduling in both S and PV loops.
// ---------------------------------------------------------------------------
#define AROWB 144
#define AQH 0
#define AQL 18432
#define KVS 36864
#define KVSTAGE 18432              // K(9216) + V(9216)
#define ATT_SMEM (KVS + 2 * KVSTAGE)   // 73728

__device__ __forceinline__ void att_issue_kv(
    const __half* const* kvb, uint32_t sb, int st, int kt, int tid)
{
    #pragma unroll
    for (int t = 0; t < 4; t++) {
        const int flat = t * 256 + tid;
        const int p = flat >> 9;
        const int ch = flat & 511;
        const int row = ch >> 3, q = ch & 7;
        cp16(sb + KVS + st * KVSTAGE + p * 9216 + row * AROWB + (q << 4),
             kvb[p] + ((size_t)kt * 64 + row) * PDK + q * 8);
    }
}

__global__ __launch_bounds__(256) void attn_tc_kernel()
{
    extern __shared__ __align__(16) char smem[];
    const uint32_t sb = smem_u32(smem);
    const int tid = threadIdx.x, wid = tid >> 5, lid = tid & 31;
    const int qt = blockIdx.x, hh = blockIdx.y, bidx = blockIdx.z;

    const size_t headoff = ((size_t)bidx * PH + hh) * PT * PDK;
    const __half* qhb = g_qh + headoff + (size_t)qt * 128 * PDK;
    const __half* qlb = g_ql + headoff + (size_t)qt * 128 * PDK;
    const __half* kvb[2] = { g_kk + headoff, g_vv + headoff };

    #pragma unroll
    for (int t = 0; t < 8; t++) {
        const int flat = t * 256 + tid;
        const int pl = flat >> 10;
        const int ch = flat & 1023;
        const int row = ch >> 3, q = ch & 7;
        cp16(sb + (pl ? AQL : AQH) + row * AROWB + (q << 4),
             (pl ? qlb : qhb) + (size_t)row * PDK + q * 8);
    }
    att_issue_kv(kvb, sb, 0, 0, tid);
    CP_COMMIT();

    float oc[8][4];
    #pragma unroll
    for (int nt = 0; nt < 8; nt++)
        #pragma unroll
        for (int e = 0; e < 4; e++) oc[nt][e] = 0.0f;
    float mrow[2] = {-CUDART_INF_F, -CUDART_INF_F};
    float lrow[2] = {0.0f, 0.0f};

    const int lr = lid & 15, lh = lid >> 4;

    for (int kt = 0; kt < PT / 64; kt++) {
        const int cur = kt & 1;
        if (kt + 1 < PT / 64) {
            att_issue_kv(kvb, sb, (kt + 1) & 1, kt + 1, tid);
            CP_COMMIT();
            CP_WAIT(1);
        } else {
            CP_WAIT(0);
        }
        __syncthreads();

        const uint32_t k0 = sb + KVS + cur * KVSTAGE;
        const uint32_t v0 = k0 + 9216;

        // S = Q K^T  — load all K frags, then hi pass across 8 accs, then lo.
        float sc[8][4];
        #pragma unroll
        for (int nt = 0; nt < 8; nt++)
            #pragma unroll
            for (int e = 0; e < 4; e++) sc[nt][e] = 0.0f;
        #pragma unroll
        for (int k16 = 0; k16 < 4; k16++) {
            const uint32_t colb = (uint32_t)((k16 * 16 + lh * 8) * 2);
            uint32_t aqh[4], aql[4];
            const uint32_t qra = (uint32_t)((wid * 16 + lr) * AROWB) + colb;
            ldsm_x4(sb + AQH + qra, aqh[0], aqh[1], aqh[2], aqh[3]);
            ldsm_x4(sb + AQL + qra, aql[0], aql[1], aql[2], aql[3]);
            uint32_t kf[4][4];
            #pragma unroll
            for (int np = 0; np < 4; np++) {
                const uint32_t kra = (uint32_t)((np * 16 + lr) * AROWB) + colb;
                ldsm_x4(k0 + kra, kf[np][0], kf[np][1], kf[np][2], kf[np][3]);
            }
            #pragma unroll
            for (int np = 0; np < 4; np++) {
                mma16816(sc[2 * np], aqh, kf[np][0], kf[np][2]);
                mma16816(sc[2 * np + 1], aqh, kf[np][1], kf[np][3]);
            }
            #pragma unroll
            for (int np = 0; np < 4; np++) {
                mma16816(sc[2 * np], aql, kf[np][0], kf[np][2]);
                mma16816(sc[2 * np + 1], aql, kf[np][1], kf[np][3]);
            }
        }

        // Online softmax
        #pragma unroll
        for (int i = 0; i < 2; i++) {
            float mx = -CUDART_INF_F;
            #pragma unroll
            for (int nt = 0; nt < 8; nt++)
                mx = fmaxf(mx, fmaxf(sc[nt][2 * i], sc[nt][2 * i + 1]));
            mx = fmaxf(mx, __shfl_xor_sync(0xffffffffu, mx, 1));
            mx = fmaxf(mx, __shfl_xor_sync(0xffffffffu, mx, 2));
            const float mnew = fmaxf(mrow[i], mx);
            const float alpha = __expf(mrow[i] - mnew);
            mrow[i] = mnew;
            float rs = 0.0f;
            #pragma unroll
            for (int nt = 0; nt < 8; nt++) {
                const float p0 = __expf(sc[nt][2 * i] - mnew);
                const float p1 = __expf(sc[nt][2 * i + 1] - mnew);
                sc[nt][2 * i] = p0; sc[nt][2 * i + 1] = p1;
                rs += p0 + p1;
            }
            rs += __shfl_xor_sync(0xffffffffu, rs, 1);
            rs += __shfl_xor_sync(0xffffffffu, rs, 2);
            lrow[i] = lrow[i] * alpha + rs;
            #pragma unroll
            for (int nt = 0; nt < 8; nt++) {
                oc[nt][2 * i] *= alpha;
                oc[nt][2 * i + 1] *= alpha;
            }
        }

        // O += P V — pack all P frags, load all V frags, hi pass then lo pass.
        uint32_t aph[4][4], apl[4][4];
        #pragma unroll
        for (int j16 = 0; j16 < 4; j16++) {
            pack_split_h(sc[2 * j16][0], sc[2 * j16][1], aph[j16][0], apl[j16][0]);
            pack_split_h(sc[2 * j16][2], sc[2 * j16][3], aph[j16][1], apl[j16][1]);
            pack_split_h(sc[2 * j16 + 1][0], sc[2 * j16 + 1][1], aph[j16][2], apl[j16][2]);
            pack_split_h(sc[2 * j16 + 1][2], sc[2 * j16 + 1][3], aph[j16][3], apl[j16][3]);
        }
        #pragma unroll
        for (int dp = 0; dp < 4; dp++) {
            uint32_t vf[4][4];
            #pragma unroll
            for (int j16 = 0; j16 < 4; j16++) {
                const uint32_t vra = (uint32_t)((j16 * 16 + lr) * AROWB
                                                + (dp * 16 + lh * 8) * 2);
                ldsm_x4t(v0 + vra, vf[j16][0], vf[j16][1], vf[j16][2], vf[j16][3]);
            }
            #pragma unroll
            for (int j16 = 0; j16 < 4; j16++) {
                mma16816(oc[2 * dp], aph[j16], vf[j16][0], vf[j16][1]);
                mma16816(oc[2 * dp + 1], aph[j16], vf[j16][2], vf[j16][3]);
            }
            #pragma unroll
            for (int j16 = 0; j16 < 4; j16++) {
                mma16816(oc[2 * dp], apl[j16], vf[j16][0], vf[j16][1]);
                mma16816(oc[2 * dp + 1], apl[j16], vf[j16][2], vf[j16][3]);
            }
        }
        __syncthreads();
    }

    // Epilogue: normalize, write y hi/lo planes [B,T,C]
    const int r0 = lid >> 2, c0 = (lid & 3) << 1;
    #pragma unroll
    for (int i = 0; i < 2; i++) {
        const float inv = 1.0f / lrow[i];
        const int tok = qt * 128 + wid * 16 + r0 + i * 8;
        const size_t rowoff = ((size_t)bidx * PT + tok) * PC + hh * PDK;
        #pragma unroll
        for (int nt = 0; nt < 8; nt++) {
            uint32_t h, l;
            pack_split_h(oc[nt][2 * i] * inv, oc[nt][2 * i + 1] * inv, h, l);
            *(uint32_t*)(g_yh + rowoff + nt * 8 + c0) = h;
            *(uint32_t*)(g_yl + rowoff + nt * 8 + c0) = l;
        }
    }
}

// ---------------------------------------------------------------------------
extern "C" void kernel_launch(void* const* d_in, const int* in_sizes, int n_in,
                              void* d_out, int out_size)
{
    const float* x      = (const float*)d_in[0];
    const float* w_attn = (const float*)d_in[1];
    const float* b_attn = (const float*)d_in[2];
    const float* w_proj = (const float*)d_in[3];
    const float* b_proj = (const float*)d_in[4];
    float* out = (float*)d_out;

    cudaFuncSetAttribute(tc_gemm_kernel<0>,
                         cudaFuncAttributeMaxDynamicSharedMemorySize, GK_SMEM);
    cudaFuncSetAttribute(tc_gemm_kernel<1>,
                         cudaFuncAttributeMaxDynamicSharedMemorySize, GK_SMEM);
    cudaFuncSetAttribute(attn_tc_kernel,
                         cudaFuncAttributeMaxDynamicSharedMemorySize, ATT_SMEM);

    __half *xh, *xl, *yh, *yl, *wa, *wp;
    cudaGetSymbolAddress((void**)&xh, g_xh);  cudaGetSymbolAddress((void**)&xl, g_xl);
    cudaGetSymbolAddress((void**)&yh, g_yh);  cudaGetSymbolAddress((void**)&yl, g_yl);
    cudaGetSymbolAddress((void**)&wa, g_wa);  cudaGetSymbolAddress((void**)&wp, g_wp);

    conv_split_kernel<<<NTOK * PC / 1024, 256>>>(x, xh, xl);
    conv_single_kernel<<<M3 * PC / 1024, 256>>>(w_attn, wa);
    conv_single_kernel<<<PC * PC / 1024, 256>>>(w_proj, wp);

    tc_gemm_kernel<0><<<dim3(M3 / 128, NTOK / 128), 256, GK_SMEM>>>(
        xh, xl, wa, b_attn, nullptr);

    attn_tc_kernel<<<dim3(PT / 128, PH, PB), 256, ATT_SMEM>>>();

    tc_gemm_kernel<1><<<dim3(PC / 128, NTOK / 128), 256, GK_SMEM>>>(
        yh, yl, wp, b_proj, out);
}

// round 14
// speedup vs baseline: 1.6896x; 1.6896x over previous
#include <cuda_runtime.h>
#include <cuda_fp16.h>
#include <math_constants.h>
#include <cstdint>

// Problem constants
#define PB 4
#define PT 2048
#define PC 1024
#define PH 16
#define PDK 64
#define NTOK (PB * PT)      // 8192
#define M3 (3 * PC)         // 3072

// Single fp16 planes everywhere (q pre-scaled by 1/8)
__device__ __half g_x16[NTOK * PC];
__device__ __half g_y16[NTOK * PC];
__device__ __half g_wa[M3 * PC];
__device__ __half g_wp[PC * PC];
__device__ __half g_q16[NTOK * PC];
__device__ __half g_k16[NTOK * PC];
__device__ __half g_v16[NTOK * PC];

// ---------------------------------------------------------------------------
// Helpers
// ---------------------------------------------------------------------------
__device__ __forceinline__ uint32_t smem_u32(const void* p) {
    uint32_t a;
    asm("{ .reg .u64 t; cvta.to.shared.u64 t, %1; cvt.u32.u64 %0, t; }"
        : "=r"(a) : "l"(p));
    return a;
}
__device__ __forceinline__ void cp16(uint32_t dst, const void* src) {
    asm volatile("cp.async.cg.shared.global [%0], [%1], 16;"
                 :: "r"(dst), "l"(src));
}
#define CP_COMMIT() asm volatile("cp.async.commit_group;" ::: "memory")
#define CP_WAIT(n)  asm volatile("cp.async.wait_group %0;" :: "n"(n) : "memory")

__device__ __forceinline__ void ldsm_x4(uint32_t addr, uint32_t& r0, uint32_t& r1,
                                        uint32_t& r2, uint32_t& r3) {
    asm volatile("ldmatrix.sync.aligned.m8n8.x4.shared.b16 {%0,%1,%2,%3}, [%4];"
                 : "=r"(r0), "=r"(r1), "=r"(r2), "=r"(r3) : "r"(addr));
}
__device__ __forceinline__ void ldsm_x4t(uint32_t addr, uint32_t& r0, uint32_t& r1,
                                         uint32_t& r2, uint32_t& r3) {
    asm volatile("ldmatrix.sync.aligned.m8n8.x4.trans.shared.b16 {%0,%1,%2,%3}, [%4];"
                 : "=r"(r0), "=r"(r1), "=r"(r2), "=r"(r3) : "r"(addr));
}
__device__ __forceinline__ void mma16816(float* c, const uint32_t* a,
                                         uint32_t b0, uint32_t b1) {
    asm volatile(
        "mma.sync.aligned.m16n8k16.row.col.f32.f16.f16.f32 "
        "{%0,%1,%2,%3}, {%4,%5,%6,%7}, {%8,%9}, {%0,%1,%2,%3};"
        : "+f"(c[0]), "+f"(c[1]), "+f"(c[2]), "+f"(c[3])
        : "r"(a[0]), "r"(a[1]), "r"(a[2]), "r"(a[3]), "r"(b0), "r"(b1));
}
__device__ __forceinline__ uint32_t pack_h2(float a, float b) {
    __half2 h = __floats2half2_rn(a, b);
    return *(const uint32_t*)&h;
}

// ---------------------------------------------------------------------------
// Conversion: fp32 -> fp16
// ---------------------------------------------------------------------------
__global__ __launch_bounds__(256) void conv_single_kernel(
    const float* __restrict__ src, __half* __restrict__ dst)
{
    const int i = (blockIdx.x * 256 + threadIdx.x) * 4;
    float4 v = *(const float4*)(src + i);
    *(uint2*)(dst + i) = make_uint2(pack_h2(v.x, v.y), pack_h2(v.z, v.w));
}

// ---------------------------------------------------------------------------
// Dense GEMM: D[m=token][n=feature] = A * B^T + bias (single fp16 A and B)
// Block 128x128, K-chunk 64 per stage, 2 stages, 2 smem planes.
// MODE 0: write q(x1/8)/k/v fp16. MODE 1: write fp32 out.
// ---------------------------------------------------------------------------
#define GROWB 144                   // 64 halves = 128B + 16B pad
#define PLB (128 * GROWB)           // 18432 per plane
#define STAGEB (2 * PLB)            // A, B
#define GK_SMEM (2 * STAGEB)        // 73728

__device__ __forceinline__ void gk_issue(
    const __half* const* srcs, uint32_t sbase, int st, int ks, int tid)
{
    #pragma unroll
    for (int t = 0; t < 8; t++) {
        const int flat = t * 256 + tid;
        const int p = flat >> 10;
        const int ch = flat & 1023;
        const int row = ch >> 3, q = ch & 7;
        cp16(sbase + st * STAGEB + p * PLB + row * GROWB + (q << 4),
             srcs[p] + (size_t)row * PC + ks * 64 + q * 8);
    }
}

template <int MODE>
__global__ __launch_bounds__(256, 2) void tc_gemm_kernel(
    const __half* __restrict__ A_g, const __half* __restrict__ B_g,
    const float* __restrict__ bias, float* __restrict__ outp)
{
    extern __shared__ __align__(16) char smem[];
    const uint32_t sbase = smem_u32(smem);
    const int tid = threadIdx.x;
    const int wid = tid >> 5, lid = tid & 31;
    const int wm = wid >> 2, wn = wid & 3;
    const int fb = blockIdx.x * 128;
    const int mb = blockIdx.y * 128;

    const __half* srcs[2] = { A_g + (size_t)mb * PC, B_g + (size_t)fb * PC };

    float c[4][4][4];
    #pragma unroll
    for (int i = 0; i < 4; i++)
        #pragma unroll
        for (int j = 0; j < 4; j++)
            #pragma unroll
            for (int e = 0; e < 4; e++) c[i][j][e] = 0.0f;

    gk_issue(srcs, sbase, 0, 0, tid);
    CP_COMMIT();

    const int lr = lid & 15;
    const int lh = lid >> 4;

    for (int ks = 0; ks < 16; ks++) {
        const int cur = ks & 1;
        if (ks + 1 < 16) {
            gk_issue(srcs, sbase, (ks + 1) & 1, ks + 1, tid);
            CP_COMMIT();
            CP_WAIT(1);
        } else {
            CP_WAIT(0);
        }
        __syncthreads();

        const uint32_t stb = sbase + cur * STAGEB;
        #pragma unroll
        for (int k16 = 0; k16 < 4; k16++) {
            const uint32_t colb = (uint32_t)(k16 * 32 + lh * 16);
            uint32_t af[4][4];
            #pragma unroll
            for (int mt = 0; mt < 4; mt++) {
                const uint32_t ra = (wm * 64 + mt * 16 + lr) * GROWB + colb;
                ldsm_x4(stb + 0 * PLB + ra, af[mt][0], af[mt][1], af[mt][2], af[mt][3]);
            }
            uint32_t bf[4][2];
            #pragma unroll
            for (int np = 0; np < 2; np++) {
                const uint32_t rb = (wn * 32 + np * 16 + lr) * GROWB + colb;
                uint32_t r0, r1, r2, r3;
                ldsm_x4(stb + 1 * PLB + rb, r0, r1, r2, r3);
                bf[np * 2][0] = r0; bf[np * 2][1] = r2;
                bf[np * 2 + 1][0] = r1; bf[np * 2 + 1][1] = r3;
            }
            #pragma unroll
            for (int mt = 0; mt < 4; mt++)
                #pragma unroll
                for (int nt = 0; nt < 4; nt++)
                    mma16816(c[mt][nt], af[mt], bf[nt][0], bf[nt][1]);
        }
        __syncthreads();
    }

    const int r0 = lid >> 2;
    const int c0 = (lid & 3) << 1;
    #pragma unroll
    for (int mt = 0; mt < 4; mt++) {
        #pragma unroll
        for (int nt = 0; nt < 4; nt++) {
            const int f = fb + wn * 32 + nt * 8 + c0;
            const float2 b2 = *(const float2*)(bias + f);
            const int tok0 = mb + wm * 64 + mt * 16 + r0;
            float2 v0 = make_float2(c[mt][nt][0] + b2.x, c[mt][nt][1] + b2.y);
            float2 v1 = make_float2(c[mt][nt][2] + b2.x, c[mt][nt][3] + b2.y);
            if (MODE == 0) {
                const int sec = f >> 10;
                const int cc = f & (PC - 1);
                const int hh = cc >> 6, d = cc & 63;
                const int b = tok0 >> 11;
                const int tk = tok0 & (PT - 1);
                const size_t base = (((size_t)b * PH + hh) * PT + tk) * PDK + d;
                const float sc = (sec == 0) ? 0.125f : 1.0f;
                __half* dst = (sec == 0) ? g_q16 : (sec == 1) ? g_k16 : g_v16;
                *(uint32_t*)(dst + base) = pack_h2(v0.x * sc, v0.y * sc);
                *(uint32_t*)(dst + base + 8 * PDK) = pack_h2(v1.x * sc, v1.y * sc);
            } else {
                *(float2*)(outp + (size_t)tok0 * PC + f) = v0;
                *(float2*)(outp + (size_t)(tok0 + 8) * PC + f) = v1;
            }
        }
    }
}

// ---------------------------------------------------------------------------
// Flash attention. Br=128, Bc=64, dk=64. Single fp16 Q (pre-scaled), K, V.
// ---------------------------------------------------------------------------
#define AROWB 144
#define AQ0 0
#define KVS 18432                  // after Q plane
#define KVSTAGE 18432              // K(9216) + V(9216)
#define ATT_SMEM (KVS + 2 * KVSTAGE)   // 55296

__device__ __forceinline__ void att_issue_kv(
    const __half* const* kvb, uint32_t sb, int st, int kt, int tid)
{
    #pragma unroll
    for (int t = 0; t < 4; t++) {
        const int flat = t * 256 + tid;
        const int p = flat >> 9;
        const int ch = flat & 511;
        const int row = ch >> 3, q = ch & 7;
        cp16(sb + KVS + st * KVSTAGE + p * 9216 + row * AROWB + (q << 4),
             kvb[p] + ((size_t)kt * 64 + row) * PDK + q * 8);
    }
}

__global__ __launch_bounds__(256) void attn_tc_kernel()
{
    extern __shared__ __align__(16) char smem[];
    const uint32_t sb = smem_u32(smem);
    const int tid = threadIdx.x, wid = tid >> 5, lid = tid & 31;
    const int qt = blockIdx.x, hh = blockIdx.y, bidx = blockIdx.z;

    const size_t headoff = ((size_t)bidx * PH + hh) * PT * PDK;
    const __half* qb = g_q16 + headoff + (size_t)qt * 128 * PDK;
    const __half* kvb[2] = { g_k16 + headoff, g_v16 + headoff };

    // Q plane (128 x 64) + KV stage 0
    #pragma unroll
    for (int t = 0; t < 4; t++) {
        const int flat = t * 256 + tid;
        const int row = flat >> 3, q = flat & 7;
        cp16(sb + AQ0 + row * AROWB + (q << 4), qb + (size_t)row * PDK + q * 8);
    }
    att_issue_kv(kvb, sb, 0, 0, tid);
    CP_COMMIT();

    float oc[8][4];
    #pragma unroll
    for (int nt = 0; nt < 8; nt++)
        #pragma unroll
        for (int e = 0; e < 4; e++) oc[nt][e] = 0.0f;
    float mrow[2] = {-CUDART_INF_F, -CUDART_INF_F};
    float lrow[2] = {0.0f, 0.0f};

    const int lr = lid & 15, lh = lid >> 4;

    for (int kt = 0; kt < PT / 64; kt++) {
        const int cur = kt & 1;
        if (kt + 1 < PT / 64) {
            att_issue_kv(kvb, sb, (kt + 1) & 1, kt + 1, tid);
            CP_COMMIT();
            CP_WAIT(1);
        } else {
            CP_WAIT(0);
        }
        __syncthreads();

        const uint32_t k0 = sb + KVS + cur * KVSTAGE;
        const uint32_t v0 = k0 + 9216;

        // S = Q K^T
        float sc[8][4];
        #pragma unroll
        for (int nt = 0; nt < 8; nt++)
            #pragma unroll
            for (int e = 0; e < 4; e++) sc[nt][e] = 0.0f;
        #pragma unroll
        for (int k16 = 0; k16 < 4; k16++) {
            const uint32_t colb = (uint32_t)((k16 * 16 + lh * 8) * 2);
            uint32_t aq[4];
            const uint32_t qra = (uint32_t)((wid * 16 + lr) * AROWB) + colb;
            ldsm_x4(sb + AQ0 + qra, aq[0], aq[1], aq[2], aq[3]);
            #pragma unroll
            for (int np = 0; np < 4; np++) {
                const uint32_t kra = (uint32_t)((np * 16 + lr) * AROWB) + colb;
                uint32_t h0, h1, h2, h3;
                ldsm_x4(k0 + kra, h0, h1, h2, h3);
                mma16816(sc[2 * np], aq, h0, h2);
                mma16816(sc[2 * np + 1], aq, h1, h3);
            }
        }

        // Online softmax
        #pragma unroll
        for (int i = 0; i < 2; i++) {
            float mx = -CUDART_INF_F;
            #pragma unroll
            for (int nt = 0; nt < 8; nt++)
                mx = fmaxf(mx, fmaxf(sc[nt][2 * i], sc[nt][2 * i + 1]));
            mx = fmaxf(mx, __shfl_xor_sync(0xffffffffu, mx, 1));
            mx = fmaxf(mx, __shfl_xor_sync(0xffffffffu, mx, 2));
            const float mnew = fmaxf(mrow[i], mx);
            const float alpha = __expf(mrow[i] - mnew);
            mrow[i] = mnew;
            float rs = 0.0f;
            #pragma unroll
            for (int nt = 0; nt < 8; nt++) {
                const float p0 = __expf(sc[nt][2 * i] - mnew);
                const float p1 = __expf(sc[nt][2 * i + 1] - mnew);
                sc[nt][2 * i] = p0; sc[nt][2 * i + 1] = p1;
                rs += p0 + p1;
            }
            rs += __shfl_xor_sync(0xffffffffu, rs, 1);
            rs += __shfl_xor_sync(0xffffffffu, rs, 2);
            lrow[i] = lrow[i] * alpha + rs;
            #pragma unroll
            for (int nt = 0; nt < 8; nt++) {
                oc[nt][2 * i] *= alpha;
                oc[nt][2 * i + 1] *= alpha;
            }
        }

        // O += P V  (P packed single fp16)
        #pragma unroll
        for (int j16 = 0; j16 < 4; j16++) {
            uint32_t ap[4];
            ap[0] = pack_h2(sc[2 * j16][0], sc[2 * j16][1]);
            ap[1] = pack_h2(sc[2 * j16][2], sc[2 * j16][3]);
            ap[2] = pack_h2(sc[2 * j16 + 1][0], sc[2 * j16 + 1][1]);
            ap[3] = pack_h2(sc[2 * j16 + 1][2], sc[2 * j16 + 1][3]);
            #pragma unroll
            for (int dp = 0; dp < 4; dp++) {
                const uint32_t vra = (uint32_t)((j16 * 16 + lr) * AROWB
                                                + (dp * 16 + lh * 8) * 2);
                uint32_t h0, h1, h2, h3;
                ldsm_x4t(v0 + vra, h0, h1, h2, h3);
                mma16816(oc[2 * dp], ap, h0, h1);
                mma16816(oc[2 * dp + 1], ap, h2, h3);
            }
        }
        __syncthreads();
    }

    // Epilogue: normalize, write y fp16 [B,T,C]
    const int r0 = lid >> 2, c0 = (lid & 3) << 1;
    #pragma unroll
    for (int i = 0; i < 2; i++) {
        const float inv = 1.0f / lrow[i];
        const int tok = qt * 128 + wid * 16 + r0 + i * 8;
        const size_t rowoff = ((size_t)bidx * PT + tok) * PC + hh * PDK;
        #pragma unroll
        for (int nt = 0; nt < 8; nt++) {
            *(uint32_t*)(g_y16 + rowoff + nt * 8 + c0) =
                pack_h2(oc[nt][2 * i] * inv, oc[nt][2 * i + 1] * inv);
        }
    }
}

// ---------------------------------------------------------------------------
extern "C" void kernel_launch(void* const* d_in, const int* in_sizes, int n_in,
                              void* d_out, int out_size)
{
    const float* x      = (const float*)d_in[0];
    const float* w_attn = (const float*)d_in[1];
    const float* b_attn = (const float*)d_in[2];
    const float* w_proj = (const float*)d_in[3];
    const float* b_proj = (const float*)d_in[4];
    float* out = (float*)d_out;

    cudaFuncSetAttribute(tc_gemm_kernel<0>,
                         cudaFuncAttributeMaxDynamicSharedMemorySize, GK_SMEM);
    cudaFuncSetAttribute(tc_gemm_kernel<1>,
                         cudaFuncAttributeMaxDynamicSharedMemorySize, GK_SMEM);
    cudaFuncSetAttribute(attn_tc_kernel,
                         cudaFuncAttributeMaxDynamicSharedMemorySize, ATT_SMEM);

    __half *x16, *y16, *wa, *wp;
    cudaGetSymbolAddress((void**)&x16, g_x16);
    cudaGetSymbolAddress((void**)&y16, g_y16);
    cudaGetSymbolAddress((void**)&wa, g_wa);
    cudaGetSymbolAddress((void**)&wp, g_wp);

    conv_single_kernel<<<NTOK * PC / 1024, 256>>>(x, x16);
    conv_single_kernel<<<M3 * PC / 1024, 256>>>(w_attn, wa);
    conv_single_kernel<<<PC * PC / 1024, 256>>>(w_proj, wp);

    tc_gemm_kernel<0><<<dim3(M3 / 128, NTOK / 128), 256, GK_SMEM>>>(
        x16, wa, b_attn, nullptr);

    attn_tc_kernel<<<dim3(PT / 128, PH, PB), 256, ATT_SMEM>>>();

    tc_gemm_kernel<1><<<dim3(PC / 128, NTOK / 128), 256, GK_SMEM>>>(
        y16, wp, b_proj, out);
}

// round 15
// speedup vs baseline: 1.7609x; 1.0422x over previous
#include <cuda_runtime.h>
#include <cuda_fp16.h>
#include <math_constants.h>
#include <cstdint>

// Problem constants
#define PB 4
#define PT 2048
#define PC 1024
#define PH 16
#define PDK 64
#define NTOK (PB * PT)      // 8192
#define M3 (3 * PC)         // 3072

// Single fp16 planes everywhere (q pre-scaled by 1/8)
__device__ __half g_x16[NTOK * PC];
__device__ __half g_y16[NTOK * PC];
__device__ __half g_wa[M3 * PC];
__device__ __half g_wp[PC * PC];
__device__ __half g_q16[NTOK * PC];
__device__ __half g_k16[NTOK * PC];
__device__ __half g_v16[NTOK * PC];

// ---------------------------------------------------------------------------
// Helpers
// ---------------------------------------------------------------------------
__device__ __forceinline__ uint32_t smem_u32(const void* p) {
    uint32_t a;
    asm("{ .reg .u64 t; cvta.to.shared.u64 t, %1; cvt.u32.u64 %0, t; }"
        : "=r"(a) : "l"(p));
    return a;
}
__device__ __forceinline__ void cp16(uint32_t dst, const void* src) {
    asm volatile("cp.async.cg.shared.global [%0], [%1], 16;"
                 :: "r"(dst), "l"(src));
}
#define CP_COMMIT() asm volatile("cp.async.commit_group;" ::: "memory")
#define CP_WAIT(n)  asm volatile("cp.async.wait_group %0;" :: "n"(n) : "memory")

__device__ __forceinline__ void ldsm_x4(uint32_t addr, uint32_t& r0, uint32_t& r1,
                                        uint32_t& r2, uint32_t& r3) {
    asm volatile("ldmatrix.sync.aligned.m8n8.x4.shared.b16 {%0,%1,%2,%3}, [%4];"
                 : "=r"(r0), "=r"(r1), "=r"(r2), "=r"(r3) : "r"(addr));
}
__device__ __forceinline__ void ldsm_x4t(uint32_t addr, uint32_t& r0, uint32_t& r1,
                                         uint32_t& r2, uint32_t& r3) {
    asm volatile("ldmatrix.sync.aligned.m8n8.x4.trans.shared.b16 {%0,%1,%2,%3}, [%4];"
                 : "=r"(r0), "=r"(r1), "=r"(r2), "=r"(r3) : "r"(addr));
}
__device__ __forceinline__ void mma16816(float* c, const uint32_t* a,
                                         uint32_t b0, uint32_t b1) {
    asm volatile(
        "mma.sync.aligned.m16n8k16.row.col.f32.f16.f16.f32 "
        "{%0,%1,%2,%3}, {%4,%5,%6,%7}, {%8,%9}, {%0,%1,%2,%3};"
        : "+f"(c[0]), "+f"(c[1]), "+f"(c[2]), "+f"(c[3])
        : "r"(a[0]), "r"(a[1]), "r"(a[2]), "r"(a[3]), "r"(b0), "r"(b1));
}
__device__ __forceinline__ uint32_t pack_h2(float a, float b) {
    __half2 h = __floats2half2_rn(a, b);
    return *(const uint32_t*)&h;
}

// ---------------------------------------------------------------------------
// Conversion: fp32 -> fp16
// ---------------------------------------------------------------------------
__global__ __launch_bounds__(256) void conv_single_kernel(
    const float* __restrict__ src, __half* __restrict__ dst)
{
    const int i = (blockIdx.x * 256 + threadIdx.x) * 4;
    float4 v = *(const float4*)(src + i);
    *(uint2*)(dst + i) = make_uint2(pack_h2(v.x, v.y), pack_h2(v.z, v.w));
}

// ---------------------------------------------------------------------------
// Dense GEMM: D[m=token][n=feature] = A * B^T + bias (single fp16 A and B)
// Block 128x128, K-chunk 64, 3-stage cp.async ring, ONE sync per k-iter.
// MODE 0: write q(x1/8)/k/v fp16. MODE 1: write fp32 out.
// ---------------------------------------------------------------------------
#define GROWB 144                   // 64 halves = 128B + 16B pad
#define PLB (128 * GROWB)           // 18432 per plane
#define STAGEB (2 * PLB)            // A, B
#define GK_SMEM (3 * STAGEB)        // 110592

__device__ __forceinline__ void gk_issue(
    const __half* const* srcs, uint32_t sbase, int st, int ks, int tid)
{
    #pragma unroll
    for (int t = 0; t < 8; t++) {
        const int flat = t * 256 + tid;
        const int p = flat >> 10;
        const int ch = flat & 1023;
        const int row = ch >> 3, q = ch & 7;
        cp16(sbase + st * STAGEB + p * PLB + row * GROWB + (q << 4),
             srcs[p] + (size_t)row * PC + ks * 64 + q * 8);
    }
}

template <int MODE>
__global__ __launch_bounds__(256, 2) void tc_gemm_kernel(
    const __half* __restrict__ A_g, const __half* __restrict__ B_g,
    const float* __restrict__ bias, float* __restrict__ outp)
{
    extern __shared__ __align__(16) char smem[];
    const uint32_t sbase = smem_u32(smem);
    const int tid = threadIdx.x;
    const int wid = tid >> 5, lid = tid & 31;
    const int wm = wid >> 2, wn = wid & 3;
    const int fb = blockIdx.x * 128;
    const int mb = blockIdx.y * 128;

    const __half* srcs[2] = { A_g + (size_t)mb * PC, B_g + (size_t)fb * PC };

    float c[4][4][4];
    #pragma unroll
    for (int i = 0; i < 4; i++)
        #pragma unroll
        for (int j = 0; j < 4; j++)
            #pragma unroll
            for (int e = 0; e < 4; e++) c[i][j][e] = 0.0f;

    gk_issue(srcs, sbase, 0, 0, tid);
    CP_COMMIT();
    gk_issue(srcs, sbase, 1, 1, tid);
    CP_COMMIT();

    const int lr = lid & 15;
    const int lh = lid >> 4;

    int cur = 0;
    for (int ks = 0; ks < 16; ks++) {
        if (ks < 14) CP_WAIT(1); else CP_WAIT(0);
        __syncthreads();

        const uint32_t stb = sbase + cur * STAGEB;
        #pragma unroll
        for (int k16 = 0; k16 < 4; k16++) {
            const uint32_t colb = (uint32_t)(k16 * 32 + lh * 16);
            uint32_t af[4][4];
            #pragma unroll
            for (int mt = 0; mt < 4; mt++) {
                const uint32_t ra = (wm * 64 + mt * 16 + lr) * GROWB + colb;
                ldsm_x4(stb + 0 * PLB + ra, af[mt][0], af[mt][1], af[mt][2], af[mt][3]);
            }
            uint32_t bf[4][2];
            #pragma unroll
            for (int np = 0; np < 2; np++) {
                const uint32_t rb = (wn * 32 + np * 16 + lr) * GROWB + colb;
                uint32_t r0, r1, r2, r3;
                ldsm_x4(stb + 1 * PLB + rb, r0, r1, r2, r3);
                bf[np * 2][0] = r0; bf[np * 2][1] = r2;
                bf[np * 2 + 1][0] = r1; bf[np * 2 + 1][1] = r3;
            }
            #pragma unroll
            for (int mt = 0; mt < 4; mt++)
                #pragma unroll
                for (int nt = 0; nt < 4; nt++)
                    mma16816(c[mt][nt], af[mt], bf[nt][0], bf[nt][1]);
        }

        if (ks + 2 < 16) {
            const int nxt = (cur + 2 >= 3) ? cur - 1 : cur + 2;
            gk_issue(srcs, sbase, nxt, ks + 2, tid);
            CP_COMMIT();
        }
        cur = (cur + 1 == 3) ? 0 : cur + 1;
    }

    const int r0 = lid >> 2;
    const int c0 = (lid & 3) << 1;
    #pragma unroll
    for (int mt = 0; mt < 4; mt++) {
        #pragma unroll
        for (int nt = 0; nt < 4; nt++) {
            const int f = fb + wn * 32 + nt * 8 + c0;
            const float2 b2 = *(const float2*)(bias + f);
            const int tok0 = mb + wm * 64 + mt * 16 + r0;
            float2 v0 = make_float2(c[mt][nt][0] + b2.x, c[mt][nt][1] + b2.y);
            float2 v1 = make_float2(c[mt][nt][2] + b2.x, c[mt][nt][3] + b2.y);
            if (MODE == 0) {
                const int sec = f >> 10;
                const int cc = f & (PC - 1);
                const int hh = cc >> 6, d = cc & 63;
                const int b = tok0 >> 11;
                const int tk = tok0 & (PT - 1);
                const size_t base = (((size_t)b * PH + hh) * PT + tk) * PDK + d;
                const float sc = (sec == 0) ? 0.125f : 1.0f;
                __half* dst = (sec == 0) ? g_q16 : (sec == 1) ? g_k16 : g_v16;
                *(uint32_t*)(dst + base) = pack_h2(v0.x * sc, v0.y * sc);
                *(uint32_t*)(dst + base + 8 * PDK) = pack_h2(v1.x * sc, v1.y * sc);
            } else {
                *(float2*)(outp + (size_t)tok0 * PC + f) = v0;
                *(float2*)(outp + (size_t)(tok0 + 8) * PC + f) = v1;
            }
        }
    }
}

// ---------------------------------------------------------------------------
// Flash attention. Br=128, Bc=64, dk=64. Single fp16 Q (pre-scaled), K, V.
// 3-stage KV ring, ONE sync per tile.
// ---------------------------------------------------------------------------
#define AROWB 144
#define AQ0 0
#define KVS 18432                  // after Q plane
#define KVSTAGE 18432              // K(9216) + V(9216)
#define ATT_SMEM (KVS + 3 * KVSTAGE)   // 73728
#define NKT (PT / 64)              // 32

__device__ __forceinline__ void att_issue_kv(
    const __half* const* kvb, uint32_t sb, int st, int kt, int tid)
{
    #pragma unroll
    for (int t = 0; t < 4; t++) {
        const int flat = t * 256 + tid;
        const int p = flat >> 9;
        const int ch = flat & 511;
        const int row = ch >> 3, q = ch & 7;
        cp16(sb + KVS + st * KVSTAGE + p * 9216 + row * AROWB + (q << 4),
             kvb[p] + ((size_t)kt * 64 + row) * PDK + q * 8);
    }
}

__global__ __launch_bounds__(256) void attn_tc_kernel()
{
    extern __shared__ __align__(16) char smem[];
    const uint32_t sb = smem_u32(smem);
    const int tid = threadIdx.x, wid = tid >> 5, lid = tid & 31;
    const int qt = blockIdx.x, hh = blockIdx.y, bidx = blockIdx.z;

    const size_t headoff = ((size_t)bidx * PH + hh) * PT * PDK;
    const __half* qb = g_q16 + headoff + (size_t)qt * 128 * PDK;
    const __half* kvb[2] = { g_k16 + headoff, g_v16 + headoff };

    // Q plane (128 x 64) + KV stages 0,1
    #pragma unroll
    for (int t = 0; t < 4; t++) {
        const int flat = t * 256 + tid;
        const int row = flat >> 3, q = flat & 7;
        cp16(sb + AQ0 + row * AROWB + (q << 4), qb + (size_t)row * PDK + q * 8);
    }
    att_issue_kv(kvb, sb, 0, 0, tid);
    CP_COMMIT();
    att_issue_kv(kvb, sb, 1, 1, tid);
    CP_COMMIT();

    float oc[8][4];
    #pragma unroll
    for (int nt = 0; nt < 8; nt++)
        #pragma unroll
        for (int e = 0; e < 4; e++) oc[nt][e] = 0.0f;
    float mrow[2] = {-CUDART_INF_F, -CUDART_INF_F};
    float lrow[2] = {0.0f, 0.0f};

    const int lr = lid & 15, lh = lid >> 4;

    int cur = 0;
    for (int kt = 0; kt < NKT; kt++) {
        if (kt < NKT - 2) CP_WAIT(1); else CP_WAIT(0);
        __syncthreads();

        const uint32_t k0 = sb + KVS + cur * KVSTAGE;
        const uint32_t v0 = k0 + 9216;

        // S = Q K^T
        float sc[8][4];
        #pragma unroll
        for (int nt = 0; nt < 8; nt++)
            #pragma unroll
            for (int e = 0; e < 4; e++) sc[nt][e] = 0.0f;
        #pragma unroll
        for (int k16 = 0; k16 < 4; k16++) {
            const uint32_t colb = (uint32_t)((k16 * 16 + lh * 8) * 2);
            uint32_t aq[4];
            const uint32_t qra = (uint32_t)((wid * 16 + lr) * AROWB) + colb;
            ldsm_x4(sb + AQ0 + qra, aq[0], aq[1], aq[2], aq[3]);
            #pragma unroll
            for (int np = 0; np < 4; np++) {
                const uint32_t kra = (uint32_t)((np * 16 + lr) * AROWB) + colb;
                uint32_t h0, h1, h2, h3;
                ldsm_x4(k0 + kra, h0, h1, h2, h3);
                mma16816(sc[2 * np], aq, h0, h2);
                mma16816(sc[2 * np + 1], aq, h1, h3);
            }
        }

        // Issue KV for kt+2 into the stage nobody is touching.
        if (kt + 2 < NKT) {
            const int nxt = (cur + 2 >= 3) ? cur - 1 : cur + 2;
            att_issue_kv(kvb, sb, nxt, kt + 2, tid);
            CP_COMMIT();
        }

        // Online softmax
        #pragma unroll
        for (int i = 0; i < 2; i++) {
            float mx = -CUDART_INF_F;
            #pragma unroll
            for (int nt = 0; nt < 8; nt++)
                mx = fmaxf(mx, fmaxf(sc[nt][2 * i], sc[nt][2 * i + 1]));
            mx = fmaxf(mx, __shfl_xor_sync(0xffffffffu, mx, 1));
            mx = fmaxf(mx, __shfl_xor_sync(0xffffffffu, mx, 2));
            const float mnew = fmaxf(mrow[i], mx);
            const float alpha = __expf(mrow[i] - mnew);
            mrow[i] = mnew;
            float rs = 0.0f;
            #pragma unroll
            for (int nt = 0; nt < 8; nt++) {
                const float p0 = __expf(sc[nt][2 * i] - mnew);
                const float p1 = __expf(sc[nt][2 * i + 1] - mnew);
                sc[nt][2 * i] = p0; sc[nt][2 * i + 1] = p1;
                rs += p0 + p1;
            }
            rs += __shfl_xor_sync(0xffffffffu, rs, 1);
            rs += __shfl_xor_sync(0xffffffffu, rs, 2);
            lrow[i] = lrow[i] * alpha + rs;
            #pragma unroll
            for (int nt = 0; nt < 8; nt++) {
                oc[nt][2 * i] *= alpha;
                oc[nt][2 * i + 1] *= alpha;
            }
        }

        // O += P V  (P packed single fp16)
        #pragma unroll
        for (int j16 = 0; j16 < 4; j16++) {
            uint32_t ap[4];
            ap[0] = pack_h2(sc[2 * j16][0], sc[2 * j16][1]);
            ap[1] = pack_h2(sc[2 * j16][2], sc[2 * j16][3]);
            ap[2] = pack_h2(sc[2 * j16 + 1][0], sc[2 * j16 + 1][1]);
            ap[3] = pack_h2(sc[2 * j16 + 1][2], sc[2 * j16 + 1][3]);
            #pragma unroll
            for (int dp = 0; dp < 4; dp++) {
                const uint32_t vra = (uint32_t)((j16 * 16 + lr) * AROWB
                                                + (dp * 16 + lh * 8) * 2);
                uint32_t h0, h1, h2, h3;
                ldsm_x4t(v0 + vra, h0, h1, h2, h3);
                mma16816(oc[2 * dp], ap, h0, h1);
                mma16816(oc[2 * dp + 1], ap, h2, h3);
            }
        }
        cur = (cur + 1 == 3) ? 0 : cur + 1;
    }

    // Epilogue: normalize, write y fp16 [B,T,C]
    const int r0 = lid >> 2, c0 = (lid & 3) << 1;
    #pragma unroll
    for (int i = 0; i < 2; i++) {
        const float inv = 1.0f / lrow[i];
        const int tok = qt * 128 + wid * 16 + r0 + i * 8;
        const size_t rowoff = ((size_t)bidx * PT + tok) * PC + hh * PDK;
        #pragma unroll
        for (int nt = 0; nt < 8; nt++) {
            *(uint32_t*)(g_y16 + rowoff + nt * 8 + c0) =
                pack_h2(oc[nt][2 * i] * inv, oc[nt][2 * i + 1] * inv);
        }
    }
}

// ---------------------------------------------------------------------------
extern "C" void kernel_launch(void* const* d_in, const int* in_sizes, int n_in,
                              void* d_out, int out_size)
{
    const float* x      = (const float*)d_in[0];
    const float* w_attn = (const float*)d_in[1];
    const float* b_attn = (const float*)d_in[2];
    const float* w_proj = (const float*)d_in[3];
    const float* b_proj = (const float*)d_in[4];
    float* out = (float*)d_out;

    cudaFuncSetAttribute(tc_gemm_kernel<0>,
                         cudaFuncAttributeMaxDynamicSharedMemorySize, GK_SMEM);
    cudaFuncSetAttribute(tc_gemm_kernel<1>,
                         cudaFuncAttributeMaxDynamicSharedMemorySize, GK_SMEM);
    cudaFuncSetAttribute(attn_tc_kernel,
                         cudaFuncAttributeMaxDynamicSharedMemorySize, ATT_SMEM);

    __half *x16, *y16, *wa, *wp;
    cudaGetSymbolAddress((void**)&x16, g_x16);
    cudaGetSymbolAddress((void**)&y16, g_y16);
    cudaGetSymbolAddress((void**)&wa, g_wa);
    cudaGetSymbolAddress((void**)&wp, g_wp);

    conv_single_kernel<<<NTOK * PC / 1024, 256>>>(x, x16);
    conv_single_kernel<<<M3 * PC / 1024, 256>>>(w_attn, wa);
    conv_single_kernel<<<PC * PC / 1024, 256>>>(w_proj, wp);

    tc_gemm_kernel<0><<<dim3(M3 / 128, NTOK / 128), 256, GK_SMEM>>>(
        x16, wa, b_attn, nullptr);

    attn_tc_kernel<<<dim3(PT / 128, PH, PB), 256, ATT_SMEM>>>();

    tc_gemm_kernel<1><<<dim3(PC / 128, NTOK / 128), 256, GK_SMEM>>>(
        y16, wp, b_proj, out);
}